// round 6
// baseline (speedup 1.0000x reference)
#include <cuda_runtime.h>

// GlobalForceNet collapses analytically (verified R3/R5: rel_err ~5e-7):
//   dist[i,i]=0 exactly -> self bias 1/(0+1e-6)=1e6 -> softmax bit-exactly
//   one-hot on self -> out = x @ A + coords @ B + c, with
//   A = W_node @ (W_v[:512]@W_f), B = W_coord @ (W_v[512:]@W_f),
//   c = b_node@Wvf_top + b_coord@Wvf_bot + b_v@W_f + b_f.
// R6: single launch; phases separated by a sense-reversing grid barrier.
// 128 blocks < 148 SMs -> all co-resident in wave 1 -> spin is safe.

#define N_NODES   8192
#define IN_DIM    256
#define HID       512
#define COORD_DIM 128
#define COMB      640   // HID + COORD_DIM
#define GRID      128
#define BLOCK     512   // 16 warps

__device__ __align__(16) float g_Wvf0[COMB];
__device__ __align__(16) float g_Wvf1[COMB];
__device__ __align__(16) float g_A0[IN_DIM];
__device__ __align__(16) float g_A1[IN_DIM];
__device__ float g_B[4];
__device__ float g_c[2];

// Grid barrier state. Ends each launch back at {0,0} (two barriers -> sense
// toggles 1 then 0), so graph replays see identical initial state.
__device__ volatile unsigned g_count = 0;
__device__ volatile unsigned g_sense = 0;

__device__ __forceinline__ void grid_barrier(unsigned& sense) {
    __syncthreads();
    if (threadIdx.x == 0) {
        sense ^= 1u;
        __threadfence();                       // make block's writes GPU-visible
        if (atomicAdd((unsigned*)&g_count, 1u) == GRID - 1) {
            g_count = 0;                       // reset before release
            __threadfence();
            g_sense = sense;                   // release
        } else {
            while (g_sense != sense) { }       // spin (volatile -> L2 polls)
        }
        __threadfence();                       // acquire
    }
    __syncthreads();
}

__device__ __forceinline__ float warp_sum(float v) {
#pragma unroll
    for (int o = 16; o; o >>= 1) v += __shfl_xor_sync(0xFFFFFFFFu, v, o);
    return v;
}

__device__ __forceinline__ float dot4(float4 a, float4 b) {
    return a.x * b.x + a.y * b.y + a.z * b.z + a.w * b.w;
}

__global__ void __launch_bounds__(BLOCK) fused_all(
        const float* __restrict__ x, const float* __restrict__ coords,
        const float* __restrict__ Wn, const float* __restrict__ bn,
        const float* __restrict__ Wc, const float* __restrict__ bc,
        const float* __restrict__ Wv, const float* __restrict__ bv,
        const float* __restrict__ Wf, const float* __restrict__ bf,
        float* __restrict__ out) {
    int tid  = threadIdx.x;
    int warp = tid >> 5, lane = tid & 31;
    int gw   = blockIdx.x * (BLOCK / 32) + warp;   // 0..2047
    unsigned bs = 0;                                // barrier sense (tid0 uses)

    // ---- Phase 1: Wvf = W_v[640,512] @ W_f[512,2]; one warp per row -------
    if (gw < COMB) {
        const float4* wv4 = reinterpret_cast<const float4*>(Wv + (size_t)gw * HID);
        const float4* wf4 = reinterpret_cast<const float4*>(Wf);
        float a0 = 0.f, a1 = 0.f;
#pragma unroll
        for (int p = 0; p < 4; ++p) {
            int q = lane + 32 * p;
            float4 v  = wv4[q];
            float4 f0 = wf4[2 * q];
            float4 f1 = wf4[2 * q + 1];
            a0 += v.x * f0.x + v.y * f0.z + v.z * f1.x + v.w * f1.z;
            a1 += v.x * f0.y + v.y * f0.w + v.z * f1.y + v.w * f1.w;
        }
        a0 = warp_sum(a0); a1 = warp_sum(a1);
        if (lane == 0) { g_Wvf0[gw] = a0; g_Wvf1[gw] = a1; }
    }
    grid_barrier(bs);

    // ---- Phase 2: A = W_node @ Wvf_top; B = W_coord @ Wvf_bot; c ----------
    if (gw < IN_DIM) {
        const float4* wn4 = reinterpret_cast<const float4*>(Wn + (size_t)gw * HID);
        const float4* w04 = reinterpret_cast<const float4*>(g_Wvf0);
        const float4* w14 = reinterpret_cast<const float4*>(g_Wvf1);
        float a0 = 0.f, a1 = 0.f;
#pragma unroll
        for (int p = 0; p < 4; ++p) {
            int q = lane + 32 * p;
            float4 v = wn4[q];
            a0 += dot4(v, w04[q]);
            a1 += dot4(v, w14[q]);
        }
        a0 = warp_sum(a0); a1 = warp_sum(a1);
        if (lane == 0) { g_A0[gw] = a0; g_A1[gw] = a1; }
    } else if (gw < IN_DIM + 4) {      // B[u] = dot(W_coord row i, Wvf_bot col j)
        int u = gw - IN_DIM, i = u >> 1, j = u & 1;
        const float4* wc4 = reinterpret_cast<const float4*>(Wc + (size_t)i * COORD_DIM);
        const float*  wvf = j ? g_Wvf1 : g_Wvf0;
        const float4* wv4 = reinterpret_cast<const float4*>(wvf + HID);
        float acc = dot4(wc4[lane], wv4[lane]);
        acc = warp_sum(acc);
        if (lane == 0) g_B[u] = acc;
    } else if (gw < IN_DIM + 6) {      // c[j]
        int j = gw - (IN_DIM + 4);
        const float* wvf = j ? g_Wvf1 : g_Wvf0;
        float acc = 0.f;
        for (int k = lane; k < HID; k += 32)       acc = fmaf(bn[k], wvf[k], acc);
        for (int k = lane; k < COORD_DIM; k += 32) acc = fmaf(bc[k], wvf[HID + k], acc);
        for (int k = lane; k < HID; k += 32)       acc = fmaf(bv[k], Wf[2 * k + j], acc);
        acc = warp_sum(acc);
        if (lane == 0) g_c[j] = acc + bf[j];
    }
    grid_barrier(bs);

    // ---- Phase 3: out[n,:] = x[n,:]@A + coords[n,:]@B + c -----------------
    // 4 rows per warp -> 8 independent front-batched LDG.128 per lane.
    int base = blockIdx.x * 64 + warp * 4;
    const float4* x4 = reinterpret_cast<const float4*>(x);
    size_t r64 = (size_t)base * 64;
    float4 v00 = x4[r64 +   0 + lane], v01 = x4[r64 +  32 + lane];
    float4 v10 = x4[r64 +  64 + lane], v11 = x4[r64 +  96 + lane];
    float4 v20 = x4[r64 + 128 + lane], v21 = x4[r64 + 160 + lane];
    float4 v30 = x4[r64 + 192 + lane], v31 = x4[r64 + 224 + lane];

    const float4* A04 = reinterpret_cast<const float4*>(g_A0);
    const float4* A14 = reinterpret_cast<const float4*>(g_A1);
    float4 w00 = A04[lane], w01 = A04[lane + 32];
    float4 w10 = A14[lane], w11 = A14[lane + 32];

    float a00 = dot4(v00, w00) + dot4(v01, w01);
    float a01 = dot4(v00, w10) + dot4(v01, w11);
    float a10 = dot4(v10, w00) + dot4(v11, w01);
    float a11 = dot4(v10, w10) + dot4(v11, w11);
    float a20 = dot4(v20, w00) + dot4(v21, w01);
    float a21 = dot4(v20, w10) + dot4(v21, w11);
    float a30 = dot4(v30, w00) + dot4(v31, w01);
    float a31 = dot4(v30, w10) + dot4(v31, w11);

#pragma unroll
    for (int o = 16; o; o >>= 1) {
        a00 += __shfl_xor_sync(0xFFFFFFFFu, a00, o);
        a01 += __shfl_xor_sync(0xFFFFFFFFu, a01, o);
        a10 += __shfl_xor_sync(0xFFFFFFFFu, a10, o);
        a11 += __shfl_xor_sync(0xFFFFFFFFu, a11, o);
        a20 += __shfl_xor_sync(0xFFFFFFFFu, a20, o);
        a21 += __shfl_xor_sync(0xFFFFFFFFu, a21, o);
        a30 += __shfl_xor_sync(0xFFFFFFFFu, a30, o);
        a31 += __shfl_xor_sync(0xFFFFFFFFu, a31, o);
    }

    if (lane < 4) {
        float s0, s1;
        if      (lane == 0) { s0 = a00; s1 = a01; }
        else if (lane == 1) { s0 = a10; s1 = a11; }
        else if (lane == 2) { s0 = a20; s1 = a21; }
        else                { s0 = a30; s1 = a31; }
        int row = base + lane;
        float2 cd = reinterpret_cast<const float2*>(coords)[row];
        float2 o2;
        o2.x = s0 + cd.x * g_B[0] + cd.y * g_B[2] + g_c[0];
        o2.y = s1 + cd.x * g_B[1] + cd.y * g_B[3] + g_c[1];
        reinterpret_cast<float2*>(out)[row] = o2;
    }
}

extern "C" void kernel_launch(void* const* d_in, const int* in_sizes, int n_in,
                              void* d_out, int out_size) {
    // metadata order: x, edge_index, initial_coords, W_node, b_node, W_coord,
    //                 b_coord, W_q, b_q, W_k, b_k, W_v, b_v, W_f, b_f
    const float* x      = (const float*)d_in[0];
    const float* coords = (const float*)d_in[2];
    const float* Wn     = (const float*)d_in[3];
    const float* bn     = (const float*)d_in[4];
    const float* Wc     = (const float*)d_in[5];
    const float* bc     = (const float*)d_in[6];
    const float* Wv     = (const float*)d_in[11];
    const float* bv     = (const float*)d_in[12];
    const float* Wf     = (const float*)d_in[13];
    const float* bf     = (const float*)d_in[14];
    float* out = (float*)d_out;

    fused_all<<<GRID, BLOCK>>>(x, coords, Wn, bn, Wc, bc, Wv, bv, Wf, bf, out);
}

// round 7
// speedup vs baseline: 1.1196x; 1.1196x over previous
#include <cuda_runtime.h>

// GlobalForceNet collapses analytically (verified R3/R5: rel_err ~5e-7):
//   softmax is bit-exactly one-hot on self -> out = x@A + coords@B + c,
//   A = W_node@(W_v[:512]@W_f), B = W_coord@(W_v[512:]@W_f),
//   c = b_node@Wvf_top + b_coord@Wvf_bot + b_v@W_f + b_f.
// R7: two launches, no grid barrier (R6 showed barriers cost more than
// graph-replay launch boundaries). Fold uses k-split partials: block b owns a
// k-chunk, computes its Wvf rows block-locally, emits partial A/B/c sums to
// per-block slots; main kernel reduces partials in a prologue hidden under
// the front-batched x loads.

#define N_NODES   8192
#define IN_DIM    256
#define HID       512
#define COORD_DIM 128
#define NCHUNK    16     // k-chunks for A (32 rows each); also m-chunks for B (8 rows)

__device__ float g_Apart0[NCHUNK * IN_DIM];   // partial A col 0, [chunk][i]
__device__ float g_Apart1[NCHUNK * IN_DIM];   // partial A col 1
__device__ float g_Bpart [NCHUNK * 4];        // partial B, [chunk][u]
__device__ float g_cA    [NCHUNK * 2];        // partial c from b_node (top)
__device__ float g_cB    [NCHUNK * 2];        // partial c from b_coord (bottom)
__device__ float g_cV    [2];                 // b_v @ W_f

__device__ __forceinline__ float warp_sum(float v) {
#pragma unroll
    for (int o = 16; o; o >>= 1) v += __shfl_xor_sync(0xFFFFFFFFu, v, o);
    return v;
}

__device__ __forceinline__ float dot4(float4 a, float4 b) {
    return a.x * b.x + a.y * b.y + a.z * b.z + a.w * b.w;
}

// Warp-cooperative: Wvf[k,j] = dot(Wv row k, Wf col j) for j=0,1.
__device__ __forceinline__ void wvf_row(const float* __restrict__ Wv,
                                        const float* __restrict__ Wf,
                                        int k, int lane, float& r0, float& r1) {
    const float4* wv4 = reinterpret_cast<const float4*>(Wv + (size_t)k * HID);
    const float4* wf4 = reinterpret_cast<const float4*>(Wf);
    float a0 = 0.f, a1 = 0.f;
#pragma unroll
    for (int p = 0; p < 4; ++p) {
        int q = lane + 32 * p;
        float4 v  = wv4[q];
        float4 f0 = wf4[2 * q];         // Wf rows 4q,4q+1 (2 cols each)
        float4 f1 = wf4[2 * q + 1];     // Wf rows 4q+2,4q+3
        a0 += v.x * f0.x + v.y * f0.z + v.z * f1.x + v.w * f1.z;
        a1 += v.x * f0.y + v.y * f0.w + v.z * f1.y + v.w * f1.w;
    }
    r0 = warp_sum(a0);
    r1 = warp_sum(a1);
}

// ---- Kernel 1: fold partials. Grid 32 x 256. --------------------------------
__global__ void __launch_bounds__(256) fold_partials(
        const float* __restrict__ Wv, const float* __restrict__ Wf,
        const float* __restrict__ Wn, const float* __restrict__ bn,
        const float* __restrict__ Wc, const float* __restrict__ bc,
        const float* __restrict__ bv) {
    __shared__ float s0[32], s1[32];
    int b    = blockIdx.x;
    int tid  = threadIdx.x;
    int warp = tid >> 5, lane = tid & 31;

    if (b < NCHUNK) {
        // ---- A-chunk: k in [32b, 32b+32) of Wvf_top --------------------------
        int k0 = 32 * b;
#pragma unroll
        for (int r = 0; r < 4; ++r) {
            int kk = warp * 4 + r;                  // 0..31
            float r0, r1;
            wvf_row(Wv, Wf, k0 + kk, lane, r0, r1);
            if (lane == 0) { s0[kk] = r0; s1[kk] = r1; }
        }
        __syncthreads();

        // Partial A rows: thread t = i, reads Wn[i, k0:k0+32] (8 float4).
        {
            int i = tid;                            // 0..255
            const float4* wn4 = reinterpret_cast<const float4*>(Wn + (size_t)i * HID + k0);
            float a0 = 0.f, a1 = 0.f;
#pragma unroll
            for (int p = 0; p < 8; ++p) {
                float4 v = wn4[p];
                int t4 = p * 4;
                a0 += v.x * s0[t4] + v.y * s0[t4+1] + v.z * s0[t4+2] + v.w * s0[t4+3];
                a1 += v.x * s1[t4] + v.y * s1[t4+1] + v.z * s1[t4+2] + v.w * s1[t4+3];
            }
            g_Apart0[b * IN_DIM + i] = a0;
            g_Apart1[b * IN_DIM + i] = a1;
        }

        // Partial c (b_node part): warp 0.
        if (warp == 0) {
            float v  = bn[k0 + lane];
            float c0 = warp_sum(v * s0[lane]);
            float c1 = warp_sum(v * s1[lane]);
            if (lane == 0) { g_cA[b * 2 + 0] = c0; g_cA[b * 2 + 1] = c1; }
        }
    } else {
        // ---- B-chunk: m in [8bb, 8bb+8) of Wvf_bot ---------------------------
        int bb = b - NCHUNK;
        int m0 = 8 * bb;
        {
            float r0, r1;
            wvf_row(Wv, Wf, HID + m0 + warp, lane, r0, r1);   // warps 0..7 -> 8 rows
            if (lane == 0) { s0[warp] = r0; s1[warp] = r1; }
        }
        __syncthreads();

        if (tid < 4) {                              // Bpart[u], u = i*2+j
            int i = tid >> 1, j = tid & 1;
            const float* sj = j ? s1 : s0;
            float acc = 0.f;
#pragma unroll
            for (int t = 0; t < 8; ++t)
                acc = fmaf(Wc[(size_t)i * COORD_DIM + m0 + t], sj[t], acc);
            g_Bpart[bb * 4 + tid] = acc;
        } else if (tid < 6) {                       // c (b_coord part)
            int j = tid - 4;
            const float* sj = j ? s1 : s0;
            float acc = 0.f;
#pragma unroll
            for (int t = 0; t < 8; ++t)
                acc = fmaf(bc[m0 + t], sj[t], acc);
            g_cB[bb * 2 + j] = acc;
        }

        if (bb == 0 && (warp == 1 || warp == 2)) {  // c (b_v @ W_f), len-512 dots
            int j = warp - 1;
            float acc = 0.f;
            for (int k = lane; k < HID; k += 32)
                acc = fmaf(bv[k], Wf[2 * k + j], acc);
            acc = warp_sum(acc);
            if (lane == 0) g_cV[j] = acc;
        }
    }
}

// ---- Kernel 2: reduce partials + main affine. Grid 128 x 512. --------------
__global__ void __launch_bounds__(512) main_affine(
        const float* __restrict__ x, const float* __restrict__ coords,
        const float* __restrict__ bf, float* __restrict__ out) {
    __shared__ __align__(16) float sA0[IN_DIM];
    __shared__ __align__(16) float sA1[IN_DIM];
    __shared__ float sB[4];
    __shared__ float sc[2];

    int tid  = threadIdx.x;
    int warp = tid >> 5, lane = tid & 31;
    int base = blockIdx.x * 64 + warp * 4;          // 4 consecutive rows

    // Front-batch x loads (independent of the prologue -> hides its latency).
    const float4* x4 = reinterpret_cast<const float4*>(x);
    size_t r64 = (size_t)base * 64;
    float4 v00 = x4[r64 +   0 + lane], v01 = x4[r64 +  32 + lane];
    float4 v10 = x4[r64 +  64 + lane], v11 = x4[r64 +  96 + lane];
    float4 v20 = x4[r64 + 128 + lane], v21 = x4[r64 + 160 + lane];
    float4 v30 = x4[r64 + 192 + lane], v31 = x4[r64 + 224 + lane];

    // Prologue: reduce the 16 partials (L2-hot, coalesced per warp).
    if (tid < IN_DIM) {
        float a = 0.f;
#pragma unroll
        for (int b = 0; b < NCHUNK; ++b) a += g_Apart0[b * IN_DIM + tid];
        sA0[tid] = a;
    } else {
        int i = tid - IN_DIM;
        float a = 0.f;
#pragma unroll
        for (int b = 0; b < NCHUNK; ++b) a += g_Apart1[b * IN_DIM + i];
        sA1[i] = a;
    }
    if (tid < 4) {
        float acc = 0.f;
#pragma unroll
        for (int bb = 0; bb < NCHUNK; ++bb) acc += g_Bpart[bb * 4 + tid];
        sB[tid] = acc;
    } else if (tid < 6) {
        int j = tid - 4;
        float acc = bf[j] + g_cV[j];
#pragma unroll
        for (int b = 0; b < NCHUNK; ++b) acc += g_cA[b * 2 + j] + g_cB[b * 2 + j];
        sc[j] = acc;
    }
    __syncthreads();

    const float4* A04 = reinterpret_cast<const float4*>(sA0);
    const float4* A14 = reinterpret_cast<const float4*>(sA1);
    float4 w00 = A04[lane], w01 = A04[lane + 32];
    float4 w10 = A14[lane], w11 = A14[lane + 32];

    float a00 = dot4(v00, w00) + dot4(v01, w01);
    float a01 = dot4(v00, w10) + dot4(v01, w11);
    float a10 = dot4(v10, w00) + dot4(v11, w01);
    float a11 = dot4(v10, w10) + dot4(v11, w11);
    float a20 = dot4(v20, w00) + dot4(v21, w01);
    float a21 = dot4(v20, w10) + dot4(v21, w11);
    float a30 = dot4(v30, w00) + dot4(v31, w01);
    float a31 = dot4(v30, w10) + dot4(v31, w11);

#pragma unroll
    for (int o = 16; o; o >>= 1) {
        a00 += __shfl_xor_sync(0xFFFFFFFFu, a00, o);
        a01 += __shfl_xor_sync(0xFFFFFFFFu, a01, o);
        a10 += __shfl_xor_sync(0xFFFFFFFFu, a10, o);
        a11 += __shfl_xor_sync(0xFFFFFFFFu, a11, o);
        a20 += __shfl_xor_sync(0xFFFFFFFFu, a20, o);
        a21 += __shfl_xor_sync(0xFFFFFFFFu, a21, o);
        a30 += __shfl_xor_sync(0xFFFFFFFFu, a30, o);
        a31 += __shfl_xor_sync(0xFFFFFFFFu, a31, o);
    }

    if (lane < 4) {
        float s0, s1;
        if      (lane == 0) { s0 = a00; s1 = a01; }
        else if (lane == 1) { s0 = a10; s1 = a11; }
        else if (lane == 2) { s0 = a20; s1 = a21; }
        else                { s0 = a30; s1 = a31; }
        int row = base + lane;
        float2 cd = reinterpret_cast<const float2*>(coords)[row];
        float2 o2;
        o2.x = s0 + cd.x * sB[0] + cd.y * sB[2] + sc[0];
        o2.y = s1 + cd.x * sB[1] + cd.y * sB[3] + sc[1];
        reinterpret_cast<float2*>(out)[row] = o2;
    }
}

extern "C" void kernel_launch(void* const* d_in, const int* in_sizes, int n_in,
                              void* d_out, int out_size) {
    // metadata order: x, edge_index, initial_coords, W_node, b_node, W_coord,
    //                 b_coord, W_q, b_q, W_k, b_k, W_v, b_v, W_f, b_f
    const float* x      = (const float*)d_in[0];
    const float* coords = (const float*)d_in[2];
    const float* Wn     = (const float*)d_in[3];
    const float* bn     = (const float*)d_in[4];
    const float* Wc     = (const float*)d_in[5];
    const float* bc     = (const float*)d_in[6];
    const float* Wv     = (const float*)d_in[11];
    const float* bv     = (const float*)d_in[12];
    const float* Wf     = (const float*)d_in[13];
    const float* bf     = (const float*)d_in[14];
    float* out = (float*)d_out;

    fold_partials<<<2 * NCHUNK, 256>>>(Wv, Wf, Wn, bn, Wc, bc, bv);
    main_affine<<<128, 512>>>(x, coords, bf, out);
}

// round 8
// speedup vs baseline: 1.2718x; 1.1359x over previous
#include <cuda_runtime.h>

// GlobalForceNet collapses analytically (verified R3/R5/R7: rel_err ~5e-7):
//   softmax is bit-exactly one-hot on self -> out = x@A + coords@B + c,
//   A = W_node@(W_v[:512]@W_f), B = W_coord@(W_v[512:]@W_f),
//   c = b_node@Wvf_top + b_coord@Wvf_bot + b_v@W_f + b_f.
// R8: 3 launches. (1) k-split fold partials, 48 blocks. (2) tiny 1-block
// reduce -> final A/B/c. (3) prologue-free main affine at high CTA count
// (R7 lesson: many co-resident CTAs beat deep per-warp MLP; per-block
// prologue forbids high grids).

#define N_NODES   8192
#define IN_DIM    256
#define HID       512
#define COORD_DIM 128
#define NCH_A     32     // A k-chunks (16 rows each)
#define NCH_B     16     // B m-chunks (8 rows each)

__device__ float g_Apart0[NCH_A * IN_DIM];
__device__ float g_Apart1[NCH_A * IN_DIM];
__device__ float g_Bpart [NCH_B * 4];
__device__ float g_cA    [NCH_A * 2];
__device__ float g_cB    [NCH_B * 2];
__device__ float g_cV    [2];

__device__ __align__(16) float g_A0[IN_DIM];
__device__ __align__(16) float g_A1[IN_DIM];
__device__ float g_Bf[4];
__device__ float g_cf[2];

__device__ __forceinline__ float warp_sum(float v) {
#pragma unroll
    for (int o = 16; o; o >>= 1) v += __shfl_xor_sync(0xFFFFFFFFu, v, o);
    return v;
}

__device__ __forceinline__ float dot4(float4 a, float4 b) {
    return a.x * b.x + a.y * b.y + a.z * b.z + a.w * b.w;
}

// Warp-cooperative: Wvf[k,j] = dot(Wv row k, Wf col j), j=0,1.
__device__ __forceinline__ void wvf_row(const float* __restrict__ Wv,
                                        const float* __restrict__ Wf,
                                        int k, int lane, float& r0, float& r1) {
    const float4* wv4 = reinterpret_cast<const float4*>(Wv + (size_t)k * HID);
    const float4* wf4 = reinterpret_cast<const float4*>(Wf);
    float a0 = 0.f, a1 = 0.f;
#pragma unroll
    for (int p = 0; p < 4; ++p) {
        int q = lane + 32 * p;
        float4 v  = wv4[q];
        float4 f0 = wf4[2 * q];
        float4 f1 = wf4[2 * q + 1];
        a0 += v.x * f0.x + v.y * f0.z + v.z * f1.x + v.w * f1.z;
        a1 += v.x * f0.y + v.y * f0.w + v.z * f1.y + v.w * f1.w;
    }
    r0 = warp_sum(a0);
    r1 = warp_sum(a1);
}

// ---- K1: fold partials. Grid 48 x 256. ------------------------------------
__global__ void __launch_bounds__(256) fold_partials(
        const float* __restrict__ Wv, const float* __restrict__ Wf,
        const float* __restrict__ Wn, const float* __restrict__ bn,
        const float* __restrict__ Wc, const float* __restrict__ bc,
        const float* __restrict__ bv) {
    __shared__ float s0[16], s1[16];
    int b    = blockIdx.x;
    int tid  = threadIdx.x;
    int warp = tid >> 5, lane = tid & 31;

    if (b < NCH_A) {
        // A-chunk: rows [16b, 16b+16) of Wvf_top. 8 warps x 2 rows.
        int k0 = 16 * b;
#pragma unroll
        for (int r = 0; r < 2; ++r) {
            int kk = warp * 2 + r;                  // 0..15
            float r0, r1;
            wvf_row(Wv, Wf, k0 + kk, lane, r0, r1);
            if (lane == 0) { s0[kk] = r0; s1[kk] = r1; }
        }
        __syncthreads();

        // Partial A row i: dot(Wn[i, k0:k0+16], s) — 4 float4 per thread.
        {
            int i = tid;
            const float4* wn4 = reinterpret_cast<const float4*>(Wn + (size_t)i * HID + k0);
            float a0 = 0.f, a1 = 0.f;
#pragma unroll
            for (int p = 0; p < 4; ++p) {
                float4 v = wn4[p];
                int t4 = p * 4;
                a0 += v.x * s0[t4] + v.y * s0[t4+1] + v.z * s0[t4+2] + v.w * s0[t4+3];
                a1 += v.x * s1[t4] + v.y * s1[t4+1] + v.z * s1[t4+2] + v.w * s1[t4+3];
            }
            g_Apart0[b * IN_DIM + i] = a0;
            g_Apart1[b * IN_DIM + i] = a1;
        }

        if (warp == 0) {                            // c partial (b_node part)
            float bnv = (lane < 16) ? bn[k0 + lane] : 0.f;
            float sv0 = (lane < 16) ? s0[lane] : 0.f;
            float sv1 = (lane < 16) ? s1[lane] : 0.f;
            float c0 = warp_sum(bnv * sv0);
            float c1 = warp_sum(bnv * sv1);
            if (lane == 0) { g_cA[b * 2 + 0] = c0; g_cA[b * 2 + 1] = c1; }
        }
    } else {
        // B-chunk: rows [8bb, 8bb+8) of Wvf_bot. Warps 0..7 -> 8 rows.
        int bb = b - NCH_A;
        int m0 = 8 * bb;
        {
            float r0, r1;
            wvf_row(Wv, Wf, HID + m0 + warp, lane, r0, r1);
            if (lane == 0) { s0[warp] = r0; s1[warp] = r1; }
        }
        __syncthreads();

        if (tid < 4) {                              // Bpart[u], u = i*2+j
            int i = tid >> 1, j = tid & 1;
            const float* sj = j ? s1 : s0;
            float acc = 0.f;
#pragma unroll
            for (int t = 0; t < 8; ++t)
                acc = fmaf(Wc[(size_t)i * COORD_DIM + m0 + t], sj[t], acc);
            g_Bpart[bb * 4 + tid] = acc;
        } else if (tid < 6) {                       // c partial (b_coord part)
            int j = tid - 4;
            const float* sj = j ? s1 : s0;
            float acc = 0.f;
#pragma unroll
            for (int t = 0; t < 8; ++t)
                acc = fmaf(bc[m0 + t], sj[t], acc);
            g_cB[bb * 2 + j] = acc;
        }

        if (bb == 0 && (warp == 1 || warp == 2)) {  // c (b_v @ W_f)
            int j = warp - 1;
            float acc = 0.f;
            for (int k = lane; k < HID; k += 32)
                acc = fmaf(bv[k], Wf[2 * k + j], acc);
            acc = warp_sum(acc);
            if (lane == 0) g_cV[j] = acc;
        }
    }
}

// ---- K2: reduce partials -> final A/B/c. 1 block x 512. --------------------
__global__ void __launch_bounds__(512) reduce_folds(const float* __restrict__ bf) {
    int tid = threadIdx.x;
    if (tid < IN_DIM) {
        float a = 0.f;
#pragma unroll
        for (int b = 0; b < NCH_A; ++b) a += g_Apart0[b * IN_DIM + tid];
        g_A0[tid] = a;
    } else {
        int i = tid - IN_DIM;
        float a = 0.f;
#pragma unroll
        for (int b = 0; b < NCH_A; ++b) a += g_Apart1[b * IN_DIM + i];
        g_A1[i] = a;
    }
    if (tid < 4) {
        float acc = 0.f;
#pragma unroll
        for (int bb = 0; bb < NCH_B; ++bb) acc += g_Bpart[bb * 4 + tid];
        g_Bf[tid] = acc;
    } else if (tid < 6) {
        int j = tid - 4;
        float acc = bf[j] + g_cV[j];
#pragma unroll
        for (int b = 0; b < NCH_A; ++b) acc += g_cA[b * 2 + j];
#pragma unroll
        for (int b = 0; b < NCH_B; ++b) acc += g_cB[b * 2 + j];
        g_cf[j] = acc;
    }
}

// ---- K3: out[n,:] = x[n,:]@A + coords[n,:]@B + c. Grid 512 x 256. ---------
// 2 rows per warp (4 front LDG.128), high CTA count, no prologue.
__global__ void __launch_bounds__(256) main_affine(
        const float* __restrict__ x, const float* __restrict__ coords,
        float* __restrict__ out) {
    __shared__ __align__(16) float sA0[IN_DIM];
    __shared__ __align__(16) float sA1[IN_DIM];
    __shared__ float sB[4];
    __shared__ float sc[2];

    int tid  = threadIdx.x;
    int warp = tid >> 5, lane = tid & 31;
    int base = blockIdx.x * 16 + warp * 2;          // 2 consecutive rows

    // Front-batch x loads (4 independent LDG.128).
    const float4* x4 = reinterpret_cast<const float4*>(x);
    size_t r64 = (size_t)base * 64;
    float4 v00 = x4[r64 +   0 + lane], v01 = x4[r64 +  32 + lane];
    float4 v10 = x4[r64 +  64 + lane], v11 = x4[r64 +  96 + lane];

    // Load A/B/c (2KB, L2-hot) while x loads are in flight.
    if (tid < IN_DIM / 4 * 2) {
        float4 a = (tid < 64)
            ? reinterpret_cast<const float4*>(g_A0)[tid]
            : reinterpret_cast<const float4*>(g_A1)[tid - 64];
        if (tid < 64) reinterpret_cast<float4*>(sA0)[tid] = a;
        else          reinterpret_cast<float4*>(sA1)[tid - 64] = a;
    }
    if (tid < 4) sB[tid] = g_Bf[tid];
    if (tid < 2) sc[tid] = g_cf[tid];
    __syncthreads();

    const float4* A04 = reinterpret_cast<const float4*>(sA0);
    const float4* A14 = reinterpret_cast<const float4*>(sA1);
    float4 w00 = A04[lane], w01 = A04[lane + 32];
    float4 w10 = A14[lane], w11 = A14[lane + 32];

    float a00 = dot4(v00, w00) + dot4(v01, w01);
    float a01 = dot4(v00, w10) + dot4(v01, w11);
    float a10 = dot4(v10, w00) + dot4(v11, w01);
    float a11 = dot4(v10, w10) + dot4(v11, w11);

#pragma unroll
    for (int o = 16; o; o >>= 1) {
        a00 += __shfl_xor_sync(0xFFFFFFFFu, a00, o);
        a01 += __shfl_xor_sync(0xFFFFFFFFu, a01, o);
        a10 += __shfl_xor_sync(0xFFFFFFFFu, a10, o);
        a11 += __shfl_xor_sync(0xFFFFFFFFu, a11, o);
    }

    if (lane < 2) {
        float s0 = (lane == 0) ? a00 : a10;
        float s1 = (lane == 0) ? a01 : a11;
        int row = base + lane;
        float2 cd = reinterpret_cast<const float2*>(coords)[row];
        float2 o2;
        o2.x = s0 + cd.x * sB[0] + cd.y * sB[2] + sc[0];
        o2.y = s1 + cd.x * sB[1] + cd.y * sB[3] + sc[1];
        reinterpret_cast<float2*>(out)[row] = o2;
    }
}

extern "C" void kernel_launch(void* const* d_in, const int* in_sizes, int n_in,
                              void* d_out, int out_size) {
    // metadata order: x, edge_index, initial_coords, W_node, b_node, W_coord,
    //                 b_coord, W_q, b_q, W_k, b_k, W_v, b_v, W_f, b_f
    const float* x      = (const float*)d_in[0];
    const float* coords = (const float*)d_in[2];
    const float* Wn     = (const float*)d_in[3];
    const float* bn     = (const float*)d_in[4];
    const float* Wc     = (const float*)d_in[5];
    const float* bc     = (const float*)d_in[6];
    const float* Wv     = (const float*)d_in[11];
    const float* bv     = (const float*)d_in[12];
    const float* Wf     = (const float*)d_in[13];
    const float* bf     = (const float*)d_in[14];
    float* out = (float*)d_out;

    fold_partials<<<NCH_A + NCH_B, 256>>>(Wv, Wf, Wn, bn, Wc, bc, bv);
    reduce_folds<<<1, 512>>>(bf);
    main_affine<<<512, 256>>>(x, coords, out);
}

// round 9
// speedup vs baseline: 1.3282x; 1.0443x over previous
#include <cuda_runtime.h>

// GlobalForceNet collapses analytically (verified R3..R8: rel_err ~5e-7):
//   softmax is bit-exactly one-hot on self -> out = x@A + coords@B + c,
//   A = W_node@(W_v[:512]@W_f), B = W_coord@(W_v[512:]@W_f),
//   c = b_node@Wvf_top + b_coord@Wvf_bot + b_v@W_f + b_f.
// R9: SINGLE launch. 48 fold blocks -> last one (atomic ticket) reduces
// partials serially (deterministic) and raises g_done. 512 main blocks
// front-batch x loads (overlap with fold), spin once on g_done, finish.
// 560 blocks x 256 thr @ <=4 blocks/SM all co-resident -> spin is safe.
// All sync state self-resets each launch (graph-replay deterministic).

#define N_NODES   8192
#define IN_DIM    256
#define HID       512
#define COORD_DIM 128
#define NCH_A     32          // A k-chunks (16 rows each)
#define NCH_B     16          // B m-chunks (8 rows each)
#define GRID_FOLD (NCH_A + NCH_B)
#define GRID_MAIN 512
#define GRID_ALL  (GRID_FOLD + GRID_MAIN)

__device__ float g_Apart0[NCH_A * IN_DIM];
__device__ float g_Apart1[NCH_A * IN_DIM];
__device__ float g_Bpart [NCH_B * 4];
__device__ float g_cA    [NCH_A * 2];
__device__ float g_cB    [NCH_B * 2];
__device__ float g_cV    [2];

__device__ __align__(16) float g_A0[IN_DIM];
__device__ __align__(16) float g_A1[IN_DIM];
__device__ float g_Bf[4];
__device__ float g_cf[2];

__device__ unsigned g_fold_cnt = 0;           // ticket for fold blocks
__device__ volatile unsigned g_done = 0;      // producer->consumer flag
__device__ unsigned g_exit_cnt = 0;           // main-block exit ticket

__device__ __forceinline__ float warp_sum(float v) {
#pragma unroll
    for (int o = 16; o; o >>= 1) v += __shfl_xor_sync(0xFFFFFFFFu, v, o);
    return v;
}

__device__ __forceinline__ float dot4(float4 a, float4 b) {
    return a.x * b.x + a.y * b.y + a.z * b.z + a.w * b.w;
}

// Warp-cooperative: Wvf[k,j] = dot(Wv row k, Wf col j), j=0,1.
__device__ __forceinline__ void wvf_row(const float* __restrict__ Wv,
                                        const float* __restrict__ Wf,
                                        int k, int lane, float& r0, float& r1) {
    const float4* wv4 = reinterpret_cast<const float4*>(Wv + (size_t)k * HID);
    const float4* wf4 = reinterpret_cast<const float4*>(Wf);
    float a0 = 0.f, a1 = 0.f;
#pragma unroll
    for (int p = 0; p < 4; ++p) {
        int q = lane + 32 * p;
        float4 v  = wv4[q];
        float4 f0 = wf4[2 * q];
        float4 f1 = wf4[2 * q + 1];
        a0 += v.x * f0.x + v.y * f0.z + v.z * f1.x + v.w * f1.z;
        a1 += v.x * f0.y + v.y * f0.w + v.z * f1.y + v.w * f1.w;
    }
    r0 = warp_sum(a0);
    r1 = warp_sum(a1);
}

__global__ void __launch_bounds__(256, 4) fused(
        const float* __restrict__ x, const float* __restrict__ coords,
        const float* __restrict__ Wn, const float* __restrict__ bn,
        const float* __restrict__ Wc, const float* __restrict__ bc,
        const float* __restrict__ Wv, const float* __restrict__ bv,
        const float* __restrict__ Wf, const float* __restrict__ bf,
        float* __restrict__ out) {
    int tid  = threadIdx.x;
    int warp = tid >> 5, lane = tid & 31;

    if (blockIdx.x < GRID_FOLD) {
        // ================= FOLD PATH =================
        __shared__ float s0[16], s1[16];
        __shared__ unsigned s_last;
        int b = blockIdx.x;

        if (b < NCH_A) {
            // A-chunk: rows [16b, 16b+16) of Wvf_top; 8 warps x 2 rows.
            int k0 = 16 * b;
#pragma unroll
            for (int r = 0; r < 2; ++r) {
                int kk = warp * 2 + r;
                float r0, r1;
                wvf_row(Wv, Wf, k0 + kk, lane, r0, r1);
                if (lane == 0) { s0[kk] = r0; s1[kk] = r1; }
            }
            __syncthreads();

            {   // Partial A row i = dot(Wn[i, k0:k0+16], s)
                int i = tid;
                const float4* wn4 = reinterpret_cast<const float4*>(Wn + (size_t)i * HID + k0);
                float a0 = 0.f, a1 = 0.f;
#pragma unroll
                for (int p = 0; p < 4; ++p) {
                    float4 v = wn4[p];
                    int t4 = p * 4;
                    a0 += v.x * s0[t4] + v.y * s0[t4+1] + v.z * s0[t4+2] + v.w * s0[t4+3];
                    a1 += v.x * s1[t4] + v.y * s1[t4+1] + v.z * s1[t4+2] + v.w * s1[t4+3];
                }
                g_Apart0[b * IN_DIM + i] = a0;
                g_Apart1[b * IN_DIM + i] = a1;
            }

            if (warp == 0) {                          // c partial (b_node)
                float bnv = (lane < 16) ? bn[k0 + lane] : 0.f;
                float sv0 = (lane < 16) ? s0[lane] : 0.f;
                float sv1 = (lane < 16) ? s1[lane] : 0.f;
                float c0 = warp_sum(bnv * sv0);
                float c1 = warp_sum(bnv * sv1);
                if (lane == 0) { g_cA[b * 2 + 0] = c0; g_cA[b * 2 + 1] = c1; }
            }
        } else {
            // B-chunk: rows [8bb, 8bb+8) of Wvf_bot; warps 0..7.
            int bb = b - NCH_A;
            int m0 = 8 * bb;
            {
                float r0, r1;
                wvf_row(Wv, Wf, HID + m0 + warp, lane, r0, r1);
                if (lane == 0) { s0[warp] = r0; s1[warp] = r1; }
            }
            __syncthreads();

            if (tid < 4) {                            // Bpart[u], u=i*2+j
                int i = tid >> 1, j = tid & 1;
                const float* sj = j ? s1 : s0;
                float acc = 0.f;
#pragma unroll
                for (int t = 0; t < 8; ++t)
                    acc = fmaf(Wc[(size_t)i * COORD_DIM + m0 + t], sj[t], acc);
                g_Bpart[bb * 4 + tid] = acc;
            } else if (tid < 6) {                     // c partial (b_coord)
                int j = tid - 4;
                const float* sj = j ? s1 : s0;
                float acc = 0.f;
#pragma unroll
                for (int t = 0; t < 8; ++t)
                    acc = fmaf(bc[m0 + t], sj[t], acc);
                g_cB[bb * 2 + j] = acc;
            }

            if (bb == 0 && (warp == 1 || warp == 2)) { // c (b_v @ W_f)
                int j = warp - 1;
                float acc = 0.f;
                for (int k = lane; k < HID; k += 32)
                    acc = fmaf(bv[k], Wf[2 * k + j], acc);
                acc = warp_sum(acc);
                if (lane == 0) g_cV[j] = acc;
            }
        }

        // Ticket: last fold block reduces everything (serial, deterministic).
        __syncthreads();
        if (tid == 0) {
            __threadfence();                           // publish partials
            s_last = (atomicAdd(&g_fold_cnt, 1u) == GRID_FOLD - 1) ? 1u : 0u;
        }
        __syncthreads();
        if (s_last) {
            __threadfence();                           // see others' partials
            {   // A: thread i sums 32 chunks for both columns.
                int i = tid;
                float a0 = 0.f, a1 = 0.f;
#pragma unroll
                for (int c = 0; c < NCH_A; ++c) {
                    a0 += g_Apart0[c * IN_DIM + i];
                    a1 += g_Apart1[c * IN_DIM + i];
                }
                g_A0[i] = a0;
                g_A1[i] = a1;
            }
            if (tid < 4) {
                float acc = 0.f;
#pragma unroll
                for (int c = 0; c < NCH_B; ++c) acc += g_Bpart[c * 4 + tid];
                g_Bf[tid] = acc;
            } else if (tid < 6) {
                int j = tid - 4;
                float acc = bf[j] + g_cV[j];
#pragma unroll
                for (int c = 0; c < NCH_A; ++c) acc += g_cA[c * 2 + j];
#pragma unroll
                for (int c = 0; c < NCH_B; ++c) acc += g_cB[c * 2 + j];
                g_cf[j] = acc;
            }
            __syncthreads();
            if (tid == 0) {
                g_fold_cnt = 0;                        // reset for next launch
                __threadfence();                       // publish A/B/c + reset
                g_done = 1;                            // release consumers
            }
        }
        return;
    }

    // ================= MAIN PATH =================
    __shared__ __align__(16) float sA0[IN_DIM];
    __shared__ __align__(16) float sA1[IN_DIM];
    __shared__ float sB[4];
    __shared__ float sc[2];

    int mid  = blockIdx.x - GRID_FOLD;                 // 0..511
    int base = mid * 16 + warp * 2;                    // 2 rows per warp

    // Front-batch x loads: in flight while fold runs.
    const float4* x4 = reinterpret_cast<const float4*>(x);
    size_t r64 = (size_t)base * 64;
    float4 v00 = x4[r64 +   0 + lane], v01 = x4[r64 +  32 + lane];
    float4 v10 = x4[r64 +  64 + lane], v11 = x4[r64 +  96 + lane];
    float2 cd0, cd1;
    if (lane < 2) cd0 = reinterpret_cast<const float2*>(coords)[base + lane];
    (void)cd1;

    // Wait for the fold flag (tid0 spins; others park at the barrier).
    if (tid == 0) {
        while (g_done == 0u) __nanosleep(64);
    }
    __syncthreads();
    __threadfence();                                   // acquire A/B/c

    if (tid < 128) {
        float4 a = (tid < 64)
            ? reinterpret_cast<const float4*>(g_A0)[tid]
            : reinterpret_cast<const float4*>(g_A1)[tid - 64];
        if (tid < 64) reinterpret_cast<float4*>(sA0)[tid] = a;
        else          reinterpret_cast<float4*>(sA1)[tid - 64] = a;
    }
    if (tid < 4) sB[tid] = g_Bf[tid];
    if (tid < 2) sc[tid] = g_cf[tid];
    __syncthreads();

    const float4* A04 = reinterpret_cast<const float4*>(sA0);
    const float4* A14 = reinterpret_cast<const float4*>(sA1);
    float4 w00 = A04[lane], w01 = A04[lane + 32];
    float4 w10 = A14[lane], w11 = A14[lane + 32];

    float a00 = dot4(v00, w00) + dot4(v01, w01);
    float a01 = dot4(v00, w10) + dot4(v01, w11);
    float a10 = dot4(v10, w00) + dot4(v11, w01);
    float a11 = dot4(v10, w10) + dot4(v11, w11);

#pragma unroll
    for (int o = 16; o; o >>= 1) {
        a00 += __shfl_xor_sync(0xFFFFFFFFu, a00, o);
        a01 += __shfl_xor_sync(0xFFFFFFFFu, a01, o);
        a10 += __shfl_xor_sync(0xFFFFFFFFu, a10, o);
        a11 += __shfl_xor_sync(0xFFFFFFFFu, a11, o);
    }

    if (lane < 2) {
        float s0v = (lane == 0) ? a00 : a10;
        float s1v = (lane == 0) ? a01 : a11;
        int row = base + lane;
        float2 o2;
        o2.x = s0v + cd0.x * sB[0] + cd0.y * sB[2] + sc[0];
        o2.y = s1v + cd0.x * sB[1] + cd0.y * sB[3] + sc[1];
        reinterpret_cast<float2*>(out)[row] = o2;
    }

    // Exit ticket: 512th main block resets the flag for the next launch.
    __syncthreads();
    if (tid == 0) {
        if (atomicAdd(&g_exit_cnt, 1u) == GRID_MAIN - 1) {
            g_exit_cnt = 0;
            __threadfence();
            g_done = 0;                                // safe: all passed spin
        }
    }
}

extern "C" void kernel_launch(void* const* d_in, const int* in_sizes, int n_in,
                              void* d_out, int out_size) {
    // metadata order: x, edge_index, initial_coords, W_node, b_node, W_coord,
    //                 b_coord, W_q, b_q, W_k, b_k, W_v, b_v, W_f, b_f
    const float* x      = (const float*)d_in[0];
    const float* coords = (const float*)d_in[2];
    const float* Wn     = (const float*)d_in[3];
    const float* bn     = (const float*)d_in[4];
    const float* Wc     = (const float*)d_in[5];
    const float* bc     = (const float*)d_in[6];
    const float* Wv     = (const float*)d_in[11];
    const float* bv     = (const float*)d_in[12];
    const float* Wf     = (const float*)d_in[13];
    const float* bf     = (const float*)d_in[14];
    float* out = (float*)d_out;

    fused<<<GRID_ALL, 256>>>(x, coords, Wn, bn, Wc, bc, Wv, bv, Wf, bf, out);
}